// round 8
// baseline (speedup 1.0000x reference)
#include <cuda_runtime.h>
#include <cuda_fp16.h>
#include <cuda_bf16.h>
#include <stdint.h>

#define N_NODES 100000
#define N_EDGES 3200000
#define DIM 128
#define DIM4 32
#define SCAN_NB 98   // ceil(100000/1024)

// ---------------- scratch (device globals) ----------------
__device__ int                g_is64;
__device__ int                g_done;
__device__ volatile int       g_flag;
__device__ unsigned long long g_dh[N_NODES];   // [40,64) = count, [0,40) = deg in 2^-24 fixed pt
__device__ float              g_dinv[N_NODES];
__device__ int                g_hist[N_NODES];
__device__ int                g_offs[N_NODES];
__device__ int                g_cursor[N_NODES];
__device__ int2               g_edge[N_EDGES];  // (src row, coef bits)
__device__ int                g_psum[128];
__device__ int                g_poff[128];
__device__ uint4              g_h16[(size_t)N_NODES * 16];  // fp16 messages: 128 halfs/row
__device__ float              g_x2[(size_t)N_NODES * DIM];  // layer-1 output (fp32)

// ---------------- edge index readers (dtype-agnostic) ----------------
__device__ __forceinline__ int read_row(const void* ei, int E, int i) {
    if (g_is64) return (int)((const long long*)ei)[i];
    return ((const int*)ei)[i];
}
__device__ __forceinline__ int read_col(const void* ei, int E, int i) {
    if (g_is64) return (int)((const long long*)ei)[(size_t)E + i];
    return ((const int*)ei)[(size_t)E + i];
}

// ---------------- f32x2 helpers ----------------
__device__ __forceinline__ unsigned long long dup2(float v) {
    unsigned long long d;
    asm("mov.b64 %0, {%1, %1};" : "=l"(d) : "f"(v));
    return d;
}
__device__ __forceinline__ unsigned long long fma2(unsigned long long a,
                                                   unsigned long long b,
                                                   unsigned long long c) {
    unsigned long long d;
    asm("fma.rn.f32x2 %0, %1, %2, %3;" : "=l"(d) : "l"(a), "l"(b), "l"(c));
    return d;
}
__device__ __forceinline__ float2 unpack2(unsigned long long v) {
    float2 f;
    f.x = __uint_as_float((unsigned)(v & 0xffffffffull));
    f.y = __uint_as_float((unsigned)(v >> 32));
    return f;
}

// ---------------- init: dh = self-loop; flags; dtype detect ----------------
__global__ void init_kernel(const int* ei_words, int n) {
    int i = blockIdx.x * blockDim.x + threadIdx.x;
    if (i < n) g_dh[i] = (1ULL << 24);
    if (i == 0) {
        g_done = 0;
        g_flag = 0;
        int is64 = 1;
        #pragma unroll 1
        for (int k = 0; k < 64; k++)
            if (ei_words[2 * k + 1] != 0) { is64 = 0; break; }
        g_is64 = is64;
    }
}

// ---------------- gemm core (device): rows [r0, r0+4) -> fp16 dst ----------------
__device__ __forceinline__ void gemm_rows(const float4* __restrict__ X4,
                                          const float* __restrict__ W,
                                          ulonglong2* Ws, uint2* H2,
                                          int r0, int n, int lane) {
    unsigned long long a01[4], a23[4];
    #pragma unroll
    for (int ri = 0; ri < 4; ri++) { a01[ri] = 0ull; a23[ri] = 0ull; }

    #pragma unroll
    for (int half = 0; half < 2; half++) {
        const ulonglong2* Wh = (const ulonglong2*)(W + (size_t)half * 64 * DIM);
        for (int idx = threadIdx.x; idx < 64 * DIM4; idx += 256)
            Ws[idx] = Wh[idx];
        __syncthreads();

        if (r0 < n) {
            #pragma unroll 4
            for (int kk = 0; kk < 16; kk++) {
                ulonglong2 w0 = Ws[(4 * kk + 0) * DIM4 + lane];
                ulonglong2 w1 = Ws[(4 * kk + 1) * DIM4 + lane];
                ulonglong2 w2 = Ws[(4 * kk + 2) * DIM4 + lane];
                ulonglong2 w3 = Ws[(4 * kk + 3) * DIM4 + lane];
                #pragma unroll
                for (int ri = 0; ri < 4; ri++) {
                    int r = r0 + ri;
                    if (r < n) {
                        float4 xv = X4[(size_t)r * DIM4 + half * 16 + kk];
                        unsigned long long x0 = dup2(xv.x), x1 = dup2(xv.y);
                        unsigned long long x2 = dup2(xv.z), x3 = dup2(xv.w);
                        a01[ri] = fma2(x0, w0.x, a01[ri]); a23[ri] = fma2(x0, w0.y, a23[ri]);
                        a01[ri] = fma2(x1, w1.x, a01[ri]); a23[ri] = fma2(x1, w1.y, a23[ri]);
                        a01[ri] = fma2(x2, w2.x, a01[ri]); a23[ri] = fma2(x2, w2.y, a23[ri]);
                        a01[ri] = fma2(x3, w3.x, a01[ri]); a23[ri] = fma2(x3, w3.y, a23[ri]);
                    }
                }
            }
        }
        __syncthreads();
    }

    #pragma unroll
    for (int ri = 0; ri < 4; ri++) {
        int r = r0 + ri;
        if (r < n) {
            float2 c01 = unpack2(a01[ri]);
            float2 c23 = unpack2(a23[ri]);
            __half2 p0 = __floats2half2_rn(c01.x, c01.y);
            __half2 p1 = __floats2half2_rn(c23.x, c23.y);
            uint2 o; o.x = *(unsigned*)&p0; o.y = *(unsigned*)&p1;
            H2[(size_t)r * 32 + lane] = o;
        }
    }
}

// ================ fused1: 1:4 interleave of gemm1 blocks and deg_hist blocks ================
// gemm block when blockIdx%5==0 (nbe == 4*nbg for this dataset); else hist block.
__global__ __launch_bounds__(256) void fused1_kernel(
        const float* __restrict__ x, const float* __restrict__ W1,
        const void* __restrict__ ei, const float* __restrict__ ew,
        int E, int n, int nbg, int nbe) {
    __shared__ ulonglong2 Ws[64 * DIM4];  // 32KB (gemm path only)

    int b = blockIdx.x;
    int g = b / 5;
    bool isG = (b % 5 == 0) && (g < nbg);

    if (!isG) {
        // ---- deg_hist block ----
        int h = b - (b + 4) / 5;              // hist block index among non-gemm blocks
        if (b % 5 == 0) h = b - g;            // overflow gemm slots fall to hist (safety)
        int i = h * 256 + threadIdx.x;
        if (i < E) {
            int c = read_col(ei, E, i);
            if ((unsigned)c < (unsigned)n) {
                unsigned long long fx =
                    (unsigned long long)__float2uint_rn(ew[i] * 16777216.0f);
                atomicAdd(&g_dh[c], (1ULL << 40) | fx);   // no return use -> REDG
            }
        }
        return;
    }

    // ---- gemm1 block: rows [g*32, g*32+32) ----
    int lane = threadIdx.x & 31, wid = threadIdx.x >> 5;
    gemm_rows((const float4*)x, W1, Ws, (uint2*)g_h16, g * 32 + wid * 4, n, lane);
}

// ================ scan_all: hist/dinv/offs in ONE kernel (co-resident grid, flag barrier) ================
__global__ __launch_bounds__(256) void scan_all(int n, int nb) {
    __shared__ int wsum[8];
    __shared__ int s_total;
    int b = blockIdx.x, tid = threadIdx.x, lane = tid & 31, wid = tid >> 5;
    int base = b * 1024 + tid * 4;

    // phase 1: load 4 contiguous dh, derive cnt + dinv (kept in regs for phase 3)
    int v0 = 0, v1 = 0, v2 = 0, v3 = 0;
    #pragma unroll
    for (int j = 0; j < 4; j++) {
        int i = base + j;
        if (i < n) {
            unsigned long long dh = g_dh[i];
            int cnt = (int)(dh >> 40);
            g_hist[i] = cnt;
            float d = (float)(dh & 0xFFFFFFFFFFULL) * (1.0f / 16777216.0f);
            g_dinv[i] = (d > 0.0f) ? rsqrtf(d) : 0.0f;
            if (j == 0) v0 = cnt; else if (j == 1) v1 = cnt;
            else if (j == 2) v2 = cnt; else v3 = cnt;
        }
    }
    int t = v0 + v1 + v2 + v3;

    // warp inclusive scan of per-thread totals
    int incl = t;
    #pragma unroll
    for (int s = 1; s < 32; s <<= 1) {
        int u = __shfl_up_sync(0xffffffffu, incl, s);
        if (lane >= s) incl += u;
    }
    if (lane == 31) wsum[wid] = incl;
    __syncthreads();
    if (tid == 0) {
        int run = 0;
        #pragma unroll
        for (int j = 0; j < 8; j++) { int u = wsum[j]; wsum[j] = run; run += u; }
        s_total = run;
        g_psum[b] = run;
        __threadfence();
        int ticket = atomicAdd(&g_done, 1);
        if (ticket == nb - 1) {
            // cross-block exclusive scan of the partials (single thread, 98 elems)
            int carry = 0;
            #pragma unroll 1
            for (int i = 0; i < SCAN_NB; i++) {
                int v = ((volatile int*)g_psum)[i];
                g_poff[i] = carry;
                carry += v;
            }
            __threadfence();
            g_flag = 1;
        }
        while (g_flag == 0) { }   // co-resident grid (98 blocks <= 148 SMs): safe spin
    }
    __syncthreads();

    int excl = g_poff[b] + wsum[wid] + incl - t;
    if (base + 0 < n) { g_offs[base + 0] = excl; g_cursor[base + 0] = excl; } excl += v0;
    if (base + 1 < n) { g_offs[base + 1] = excl; g_cursor[base + 1] = excl; } excl += v1;
    if (base + 2 < n) { g_offs[base + 2] = excl; g_cursor[base + 2] = excl; } excl += v2;
    if (base + 3 < n) { g_offs[base + 3] = excl; g_cursor[base + 3] = excl; }
}

// ---------------- scatter edges into CSR bins; single int2 store per edge ----------------
__global__ void scatter_kernel(const void* __restrict__ ei,
                               const float* __restrict__ ew, int E, int n) {
    int i = blockIdx.x * blockDim.x + threadIdx.x;
    if (i < E) {
        int r = read_row(ei, E, i);
        int c = read_col(ei, E, i);
        if ((unsigned)r >= (unsigned)n || (unsigned)c >= (unsigned)n) return;
        int pos = atomicAdd(&g_cursor[c], 1);
        if ((unsigned)pos < (unsigned)E)
            g_edge[pos] = make_int2(r, __float_as_int(ew[i] * g_dinv[r]));
    }
}

// ---------------- GEMM layer 2 (standalone): g_h16 = fp16(g_x2 @ W2) ----------------
__global__ __launch_bounds__(256) void gemm2_kernel(const float* __restrict__ W2, int n) {
    __shared__ ulonglong2 Ws[64 * DIM4];
    int lane = threadIdx.x & 31, wid = threadIdx.x >> 5;
    gemm_rows((const float4*)g_x2, W2, Ws, (uint2*)g_h16,
              blockIdx.x * 32 + wid * 4, n, lane);
}

// ---------------- pull aggregation (fp16 gather): one warp per node, 2 edges/iter ----------------
__global__ __launch_bounds__(256) void agg_kernel(const float* __restrict__ bias,
                                                  float* __restrict__ out_ext,
                                                  int n, int do_relu, int dst_is_x2) {
    int gw = (blockIdx.x * blockDim.x + threadIdx.x) >> 5;
    int lane = threadIdx.x & 31;
    if (gw >= n) return;
    int i = gw;
    int half = lane >> 4;
    int li = lane & 15;

    int off = g_offs[i];
    int end = off + g_hist[i];

    float acc[8];
    #pragma unroll
    for (int j = 0; j < 8; j++) acc[j] = 0.0f;

    #pragma unroll 2
    for (int e0 = off; e0 < end; e0 += 2) {
        int e = e0 + half;
        if (e < end) {
            int2 ed = g_edge[e];
            float c = __int_as_float(ed.y);
            uint4 v = g_h16[(size_t)ed.x * 16 + li];
            __half2* hp = (__half2*)&v;
            float2 f0 = __half22float2(hp[0]);
            float2 f1 = __half22float2(hp[1]);
            float2 f2 = __half22float2(hp[2]);
            float2 f3 = __half22float2(hp[3]);
            acc[0] += c * f0.x; acc[1] += c * f0.y;
            acc[2] += c * f1.x; acc[3] += c * f1.y;
            acc[4] += c * f2.x; acc[5] += c * f2.y;
            acc[6] += c * f3.x; acc[7] += c * f3.y;
        }
    }
    #pragma unroll
    for (int j = 0; j < 8; j++)
        acc[j] += __shfl_xor_sync(0xffffffffu, acc[j], 16);

    float di = g_dinv[i];
    float d2 = di * di;
    uint4 sv = g_h16[(size_t)i * 16 + li];
    __half2* sh = (__half2*)&sv;
    float2 s0 = __half22float2(sh[2 * half + 0]);
    float2 s1 = __half22float2(sh[2 * half + 1]);
    float4 b4 = ((const float4*)bias)[li * 2 + half];

    float4 r;
    r.x = di * acc[4 * half + 0] + d2 * s0.x + b4.x;
    r.y = di * acc[4 * half + 1] + d2 * s0.y + b4.y;
    r.z = di * acc[4 * half + 2] + d2 * s1.x + b4.z;
    r.w = di * acc[4 * half + 3] + d2 * s1.y + b4.w;
    if (do_relu) {
        r.x = fmaxf(r.x, 0.f); r.y = fmaxf(r.y, 0.f);
        r.z = fmaxf(r.z, 0.f); r.w = fmaxf(r.w, 0.f);
    }
    float4* dst = dst_is_x2 ? (float4*)g_x2 : (float4*)out_ext;
    dst[(size_t)i * 32 + li * 2 + half] = r;
}

// ---------------- launch (kernel launches ONLY — graph-capturable) ----------------
extern "C" void kernel_launch(void* const* d_in, const int* in_sizes, int n_in,
                              void* d_out, int out_size) {
    const float* x  = (const float*)d_in[0];
    const void*  ei = d_in[1];                 // [2, E], int32 OR int64
    const float* ew = (const float*)d_in[2];
    const float* W1 = (const float*)d_in[3];
    const float* b1 = (const float*)d_in[4];
    const float* W2 = (const float*)d_in[5];
    const float* b2 = (const float*)d_in[6];
    float* out = (float*)d_out;

    int n = in_sizes[0] / DIM;   // 100000
    int E = in_sizes[2];         // 3200000

    int nb_n    = (n + 255) / 256;
    int nb_e256 = (E + 255) / 256;   // 12500
    int nb_e512 = (E + 511) / 512;
    int nb_wn   = (n * 32 + 255) / 256;
    int nb_g    = (n + 31) / 32;     // 3125  (nb_e256 == 4*nb_g)
    int nb_s    = (n + 1023) / 1024; // 98

    // init (+dtype detect) -> [gemm1 ∥ deg_hist] -> fused scans -> scatter
    init_kernel<<<nb_n, 256>>>((const int*)ei, n);
    fused1_kernel<<<nb_g + nb_e256, 256>>>(x, W1, ei, ew, E, n, nb_g, nb_e256);
    scan_all<<<nb_s, 256>>>(n, nb_s);
    scatter_kernel<<<nb_e512, 512>>>(ei, ew, E, n);

    // layer 1 aggregation -> layer 2 gemm -> final aggregation
    agg_kernel<<<nb_wn, 256>>>(b1, out, n, /*relu=*/1, /*dst_is_x2=*/1);
    gemm2_kernel<<<nb_g, 256>>>(W2, n);
    agg_kernel<<<nb_wn, 256>>>(b2, out, n, /*relu=*/0, /*dst_is_x2=*/0);
}

// round 9
// speedup vs baseline: 1.0487x; 1.0487x over previous
#include <cuda_runtime.h>
#include <cuda_fp16.h>
#include <cuda_bf16.h>
#include <stdint.h>

#define N_NODES 100000
#define N_EDGES 3200000
#define DIM 128
#define DIM4 32
#define SCAN_NB 98   // ceil(100000/1024)

// ---------------- scratch (device globals) ----------------
__device__ int                g_is64;
__device__ int                g_done;
__device__ volatile int       g_flag;
__device__ unsigned long long g_dh[N_NODES];   // [40,64) = count, [0,40) = deg 2^-24 fixed pt
__device__ float              g_dinv[N_NODES];
__device__ int                g_hist[N_NODES];
__device__ int                g_offs[N_NODES];
__device__ int                g_cursor[N_NODES];
__device__ int2               g_edge[N_EDGES];  // (src row, ew bits)
__device__ int                g_psum[128];
__device__ int                g_poff[128];
__device__ uint4              g_h16[(size_t)N_NODES * 16];  // fp16 h' = dinv*h, 128 halfs/row
__device__ float              g_x2[(size_t)N_NODES * DIM];  // layer-1 output (fp32)

// ---------------- edge index readers (dtype-agnostic) ----------------
__device__ __forceinline__ int read_row(const void* ei, int E, int i) {
    if (g_is64) return (int)((const long long*)ei)[i];
    return ((const int*)ei)[i];
}
__device__ __forceinline__ int read_col(const void* ei, int E, int i) {
    if (g_is64) return (int)((const long long*)ei)[(size_t)E + i];
    return ((const int*)ei)[(size_t)E + i];
}

// ---------------- f32x2 helpers ----------------
__device__ __forceinline__ unsigned long long dup2(float v) {
    unsigned long long d;
    asm("mov.b64 %0, {%1, %1};" : "=l"(d) : "f"(v));
    return d;
}
__device__ __forceinline__ unsigned long long fma2(unsigned long long a,
                                                   unsigned long long b,
                                                   unsigned long long c) {
    unsigned long long d;
    asm("fma.rn.f32x2 %0, %1, %2, %3;" : "=l"(d) : "l"(a), "l"(b), "l"(c));
    return d;
}
__device__ __forceinline__ float2 unpack2(unsigned long long v) {
    float2 f;
    f.x = __uint_as_float((unsigned)(v & 0xffffffffull));
    f.y = __uint_as_float((unsigned)(v >> 32));
    return f;
}

// ---------------- init: dh = self-loop; flags; dtype detect ----------------
__global__ void init_kernel(const int* ei_words, int n) {
    int i = blockIdx.x * blockDim.x + threadIdx.x;
    if (i < n) g_dh[i] = (1ULL << 24);
    if (i == 0) {
        g_done = 0;
        g_flag = 0;
        int is64 = 1;
        #pragma unroll 1
        for (int k = 0; k < 64; k++)
            if (ei_words[2 * k + 1] != 0) { is64 = 0; break; }
        g_is64 = is64;
    }
}

// ---------------- deg+hist: ONE u64 reduction per edge ----------------
__global__ void deg_hist_kernel(const void* __restrict__ ei,
                                const float* __restrict__ ew, int E, int n) {
    int i = blockIdx.x * blockDim.x + threadIdx.x;
    if (i < E) {
        int c = read_col(ei, E, i);
        if ((unsigned)c >= (unsigned)n) return;
        unsigned long long fx = (unsigned long long)__float2uint_rn(ew[i] * 16777216.0f);
        atomicAdd(&g_dh[c], (1ULL << 40) | fx);   // no return use -> REDG
    }
}

// ================ scan_all: hist/dinv/offs in ONE kernel (co-resident grid) ================
__global__ __launch_bounds__(256) void scan_all(int n, int nb) {
    __shared__ int wsum[8];
    __shared__ int s_last;
    int b = blockIdx.x, tid = threadIdx.x, lane = tid & 31, wid = tid >> 5;
    int base = b * 1024 + tid * 4;

    // phase 1: derive cnt + dinv from packed dh; keep counts in regs
    int v0 = 0, v1 = 0, v2 = 0, v3 = 0;
    #pragma unroll
    for (int j = 0; j < 4; j++) {
        int i = base + j;
        if (i < n) {
            unsigned long long dh = g_dh[i];
            int cnt = (int)(dh >> 40);
            g_hist[i] = cnt;
            float d = (float)(dh & 0xFFFFFFFFFFULL) * (1.0f / 16777216.0f);
            g_dinv[i] = (d > 0.0f) ? rsqrtf(d) : 0.0f;
            if (j == 0) v0 = cnt; else if (j == 1) v1 = cnt;
            else if (j == 2) v2 = cnt; else v3 = cnt;
        }
    }
    int t = v0 + v1 + v2 + v3;

    // block scan of per-thread totals
    int incl = t;
    #pragma unroll
    for (int s = 1; s < 32; s <<= 1) {
        int u = __shfl_up_sync(0xffffffffu, incl, s);
        if (lane >= s) incl += u;
    }
    if (lane == 31) wsum[wid] = incl;
    __syncthreads();
    if (tid == 0) {
        int run = 0;
        #pragma unroll
        for (int j = 0; j < 8; j++) { int u = wsum[j]; wsum[j] = run; run += u; }
        g_psum[b] = run;
        __threadfence();
        int ticket = atomicAdd(&g_done, 1);
        s_last = (ticket == nb - 1);
    }
    __syncthreads();

    // last-arriving block: WARP-PARALLEL scan of the 98 partials
    if (s_last) {
        if (tid < 32) {
            int carry = 0;
            #pragma unroll
            for (int bb = 0; bb < SCAN_NB; bb += 32) {
                int i = bb + tid;
                int v = (i < SCAN_NB) ? ((volatile int*)g_psum)[i] : 0;
                int inc2 = v;
                #pragma unroll
                for (int st = 1; st < 32; st <<= 1) {
                    int u = __shfl_up_sync(0xffffffffu, inc2, st);
                    if (tid >= st) inc2 += u;
                }
                if (i < SCAN_NB) g_poff[i] = carry + inc2 - v;
                carry += __shfl_sync(0xffffffffu, inc2, 31);
            }
        }
        __syncthreads();
        if (tid == 0) { __threadfence(); g_flag = 1; }
    }
    if (tid == 0) { while (g_flag == 0) { } }   // 98 blocks <= 148 SMs: safe spin
    __syncthreads();

    int excl = g_poff[b] + wsum[wid] + incl - t;
    if (base + 0 < n) { g_offs[base + 0] = excl; g_cursor[base + 0] = excl; } excl += v0;
    if (base + 1 < n) { g_offs[base + 1] = excl; g_cursor[base + 1] = excl; } excl += v1;
    if (base + 2 < n) { g_offs[base + 2] = excl; g_cursor[base + 2] = excl; } excl += v2;
    if (base + 3 < n) { g_offs[base + 3] = excl; g_cursor[base + 3] = excl; }
}

// ---------------- scatter: (row, ew) — NO dinv gather ----------------
__global__ void scatter_kernel(const void* __restrict__ ei,
                               const float* __restrict__ ew, int E, int n) {
    int i = blockIdx.x * blockDim.x + threadIdx.x;
    if (i < E) {
        int r = read_row(ei, E, i);
        int c = read_col(ei, E, i);
        if ((unsigned)r >= (unsigned)n || (unsigned)c >= (unsigned)n) return;
        int pos = atomicAdd(&g_cursor[c], 1);
        if ((unsigned)pos < (unsigned)E)
            g_edge[pos] = make_int2(r, __float_as_int(ew[i]));
    }
}

// ---------------- gemm core: rows [r0,r0+4) -> fp16 h' = dinv*(x@W) ----------------
__device__ __forceinline__ void gemm_rows(const float4* __restrict__ X4,
                                          const float* __restrict__ W,
                                          ulonglong2* Ws, uint2* H2,
                                          int r0, int n, int lane) {
    unsigned long long a01[4], a23[4];
    #pragma unroll
    for (int ri = 0; ri < 4; ri++) { a01[ri] = 0ull; a23[ri] = 0ull; }

    #pragma unroll
    for (int half = 0; half < 2; half++) {
        const ulonglong2* Wh = (const ulonglong2*)(W + (size_t)half * 64 * DIM);
        for (int idx = threadIdx.x; idx < 64 * DIM4; idx += 256)
            Ws[idx] = Wh[idx];
        __syncthreads();

        if (r0 < n) {
            #pragma unroll 4
            for (int kk = 0; kk < 16; kk++) {
                ulonglong2 w0 = Ws[(4 * kk + 0) * DIM4 + lane];
                ulonglong2 w1 = Ws[(4 * kk + 1) * DIM4 + lane];
                ulonglong2 w2 = Ws[(4 * kk + 2) * DIM4 + lane];
                ulonglong2 w3 = Ws[(4 * kk + 3) * DIM4 + lane];
                #pragma unroll
                for (int ri = 0; ri < 4; ri++) {
                    int r = r0 + ri;
                    if (r < n) {
                        float4 xv = X4[(size_t)r * DIM4 + half * 16 + kk];
                        unsigned long long x0 = dup2(xv.x), x1 = dup2(xv.y);
                        unsigned long long x2 = dup2(xv.z), x3 = dup2(xv.w);
                        a01[ri] = fma2(x0, w0.x, a01[ri]); a23[ri] = fma2(x0, w0.y, a23[ri]);
                        a01[ri] = fma2(x1, w1.x, a01[ri]); a23[ri] = fma2(x1, w1.y, a23[ri]);
                        a01[ri] = fma2(x2, w2.x, a01[ri]); a23[ri] = fma2(x2, w2.y, a23[ri]);
                        a01[ri] = fma2(x3, w3.x, a01[ri]); a23[ri] = fma2(x3, w3.y, a23[ri]);
                    }
                }
            }
        }
        __syncthreads();
    }

    #pragma unroll
    for (int ri = 0; ri < 4; ri++) {
        int r = r0 + ri;
        if (r < n) {
            float dr = g_dinv[r];
            float2 c01 = unpack2(a01[ri]);
            float2 c23 = unpack2(a23[ri]);
            __half2 p0 = __floats2half2_rn(dr * c01.x, dr * c01.y);
            __half2 p1 = __floats2half2_rn(dr * c23.x, dr * c23.y);
            uint2 o; o.x = *(unsigned*)&p0; o.y = *(unsigned*)&p1;
            H2[(size_t)r * 32 + lane] = o;
        }
    }
}

__global__ __launch_bounds__(256) void gemm1_kernel(const float* __restrict__ x,
                                                    const float* __restrict__ W1, int n) {
    __shared__ ulonglong2 Ws[64 * DIM4];
    int lane = threadIdx.x & 31, wid = threadIdx.x >> 5;
    gemm_rows((const float4*)x, W1, Ws, (uint2*)g_h16, blockIdx.x * 32 + wid * 4, n, lane);
}
__global__ __launch_bounds__(256) void gemm2_kernel(const float* __restrict__ W2, int n) {
    __shared__ ulonglong2 Ws[64 * DIM4];
    int lane = threadIdx.x & 31, wid = threadIdx.x >> 5;
    gemm_rows((const float4*)g_x2, W2, Ws, (uint2*)g_h16, blockIdx.x * 32 + wid * 4, n, lane);
}

// ---------------- pull aggregation: one warp per node, 2 edges/iter, unroll 4 ----------------
// out[i] = dinv[i] * ( sum_e ew_e * h'[src_e] + h'[i] ) + b ; optional relu
__global__ __launch_bounds__(256) void agg_kernel(const float* __restrict__ bias,
                                                  float* __restrict__ out_ext,
                                                  int n, int do_relu, int dst_is_x2) {
    int gw = (blockIdx.x * blockDim.x + threadIdx.x) >> 5;
    int lane = threadIdx.x & 31;
    if (gw >= n) return;
    int i = gw;
    int half = lane >> 4;    // which of 2 concurrent edges
    int li = lane & 15;      // 16B chunk within the 256B fp16 row

    int off = g_offs[i];
    int end = off + g_hist[i];

    float acc[8];
    #pragma unroll
    for (int j = 0; j < 8; j++) acc[j] = 0.0f;

    #pragma unroll 4
    for (int e0 = off; e0 < end; e0 += 2) {
        int e = e0 + half;
        if (e < end) {
            int2 ed = g_edge[e];
            float c = __int_as_float(ed.y);
            uint4 v = g_h16[(size_t)ed.x * 16 + li];
            __half2* hp = (__half2*)&v;
            float2 f0 = __half22float2(hp[0]);
            float2 f1 = __half22float2(hp[1]);
            float2 f2 = __half22float2(hp[2]);
            float2 f3 = __half22float2(hp[3]);
            acc[0] += c * f0.x; acc[1] += c * f0.y;
            acc[2] += c * f1.x; acc[3] += c * f1.y;
            acc[4] += c * f2.x; acc[5] += c * f2.y;
            acc[6] += c * f3.x; acc[7] += c * f3.y;
        }
    }
    #pragma unroll
    for (int j = 0; j < 8; j++)
        acc[j] += __shfl_xor_sync(0xffffffffu, acc[j], 16);

    float di = g_dinv[i];
    uint4 sv = g_h16[(size_t)i * 16 + li];
    __half2* sh = (__half2*)&sv;
    float2 s0 = __half22float2(sh[2 * half + 0]);
    float2 s1 = __half22float2(sh[2 * half + 1]);
    float4 b4 = ((const float4*)bias)[li * 2 + half];

    float4 r;
    r.x = di * (acc[4 * half + 0] + s0.x) + b4.x;
    r.y = di * (acc[4 * half + 1] + s0.y) + b4.y;
    r.z = di * (acc[4 * half + 2] + s1.x) + b4.z;
    r.w = di * (acc[4 * half + 3] + s1.y) + b4.w;
    if (do_relu) {
        r.x = fmaxf(r.x, 0.f); r.y = fmaxf(r.y, 0.f);
        r.z = fmaxf(r.z, 0.f); r.w = fmaxf(r.w, 0.f);
    }
    float4* dst = dst_is_x2 ? (float4*)g_x2 : (float4*)out_ext;
    dst[(size_t)i * 32 + li * 2 + half] = r;
}

// ---------------- launch (kernel launches ONLY — graph-capturable) ----------------
extern "C" void kernel_launch(void* const* d_in, const int* in_sizes, int n_in,
                              void* d_out, int out_size) {
    const float* x  = (const float*)d_in[0];
    const void*  ei = d_in[1];                 // [2, E], int32 OR int64
    const float* ew = (const float*)d_in[2];
    const float* W1 = (const float*)d_in[3];
    const float* b1 = (const float*)d_in[4];
    const float* W2 = (const float*)d_in[5];
    const float* b2 = (const float*)d_in[6];
    float* out = (float*)d_out;

    int n = in_sizes[0] / DIM;   // 100000
    int E = in_sizes[2];         // 3200000

    int nb_n  = (n + 255) / 256;
    int nb_e  = (E + 511) / 512;
    int nb_wn = (n * 32 + 255) / 256;  // one warp per node
    int nb_g  = (n + 31) / 32;
    int nb_s  = (n + 1023) / 1024;     // 98

    // preprocessing: CSR-ize edges by destination
    init_kernel<<<nb_n, 256>>>((const int*)ei, n);
    deg_hist_kernel<<<nb_e, 512>>>(ei, ew, E, n);
    scan_all<<<nb_s, 256>>>(n, nb_s);
    scatter_kernel<<<nb_e, 512>>>(ei, ew, E, n);

    // layer 1: g_h16 = fp16(dinv * (x @ W1)) ; g_x2 = agg + b1, relu
    gemm1_kernel<<<nb_g, 256>>>(x, W1, n);
    agg_kernel<<<nb_wn, 256>>>(b1, out, n, /*relu=*/1, /*dst_is_x2=*/1);

    // layer 2: g_h16 = fp16(dinv * (g_x2 @ W2)) ; out = agg + b2
    gemm2_kernel<<<nb_g, 256>>>(W2, n);
    agg_kernel<<<nb_wn, 256>>>(b2, out, n, /*relu=*/0, /*dst_is_x2=*/0);
}

// round 11
// speedup vs baseline: 1.0651x; 1.0156x over previous
#include <cuda_runtime.h>
#include <cuda_fp16.h>
#include <cuda_bf16.h>
#include <stdint.h>

#define N_NODES 100000
#define N_EDGES 3200000
#define DIM 128
#define DIM4 32
#define SCAN_NB 98   // ceil(100000/1024)

// ---------------- scratch (device globals) ----------------
__device__ int                g_is64;
__device__ int                g_done;
__device__ volatile int       g_flag;
__device__ unsigned long long g_dh[N_NODES];   // [40,64) = count, [0,40) = deg 2^-24 fixed pt
__device__ float              g_dinv[N_NODES];
__device__ int                g_hist[N_NODES];
__device__ int                g_offs[N_NODES];
__device__ int                g_cursor[N_NODES];
__device__ int2               g_edge[N_EDGES];  // (src row, ew bits)
__device__ int                g_psum[128];
__device__ int                g_poff[128];
__device__ uint4              g_h16[(size_t)N_NODES * 16];  // fp16 h' = dinv*h, 128 halfs/row
__device__ float              g_x2[(size_t)N_NODES * DIM];  // layer-1 output (fp32)

// ---------------- edge index readers (dtype-agnostic) ----------------
__device__ __forceinline__ int read_row(const void* ei, int E, int i) {
    if (g_is64) return (int)((const long long*)ei)[i];
    return ((const int*)ei)[i];
}
__device__ __forceinline__ int read_col(const void* ei, int E, int i) {
    if (g_is64) return (int)((const long long*)ei)[(size_t)E + i];
    return ((const int*)ei)[(size_t)E + i];
}

// ---------------- f32x2 helpers ----------------
__device__ __forceinline__ unsigned long long dup2(float v) {
    unsigned long long d;
    asm("mov.b64 %0, {%1, %1};" : "=l"(d) : "f"(v));
    return d;
}
__device__ __forceinline__ unsigned long long fma2(unsigned long long a,
                                                   unsigned long long b,
                                                   unsigned long long c) {
    unsigned long long d;
    asm("fma.rn.f32x2 %0, %1, %2, %3;" : "=l"(d) : "l"(a), "l"(b), "l"(c));
    return d;
}
__device__ __forceinline__ float2 unpack2(unsigned long long v) {
    float2 f;
    f.x = __uint_as_float((unsigned)(v & 0xffffffffull));
    f.y = __uint_as_float((unsigned)(v >> 32));
    return f;
}

// ---------------- init: dh = self-loop; flags; dtype detect ----------------
__global__ void init_kernel(const int* ei_words, int n) {
    int i = blockIdx.x * blockDim.x + threadIdx.x;
    if (i < n) g_dh[i] = (1ULL << 24);
    if (i == 0) {
        g_done = 0;
        g_flag = 0;
        int is64 = 1;
        #pragma unroll 1
        for (int k = 0; k < 64; k++)
            if (ei_words[2 * k + 1] != 0) { is64 = 0; break; }
        g_is64 = is64;
    }
}

// ---------------- deg+hist: ONE u64 reduction per edge ----------------
__global__ void deg_hist_kernel(const void* __restrict__ ei,
                                const float* __restrict__ ew, int E, int n) {
    int i = blockIdx.x * blockDim.x + threadIdx.x;
    if (i < E) {
        int c = read_col(ei, E, i);
        if ((unsigned)c >= (unsigned)n) return;
        unsigned long long fx = (unsigned long long)__float2uint_rn(ew[i] * 16777216.0f);
        atomicAdd(&g_dh[c], (1ULL << 40) | fx);   // no return use -> REDG
    }
}

// ================ scan_all: hist/dinv/offs in ONE kernel (co-resident grid) ================
__global__ __launch_bounds__(256) void scan_all(int n, int nb) {
    __shared__ int wsum[8];
    __shared__ int s_last;
    int b = blockIdx.x, tid = threadIdx.x, lane = tid & 31, wid = tid >> 5;
    int base = b * 1024 + tid * 4;

    int v0 = 0, v1 = 0, v2 = 0, v3 = 0;
    #pragma unroll
    for (int j = 0; j < 4; j++) {
        int i = base + j;
        if (i < n) {
            unsigned long long dh = g_dh[i];
            int cnt = (int)(dh >> 40);
            g_hist[i] = cnt;
            float d = (float)(dh & 0xFFFFFFFFFFULL) * (1.0f / 16777216.0f);
            g_dinv[i] = (d > 0.0f) ? rsqrtf(d) : 0.0f;
            if (j == 0) v0 = cnt; else if (j == 1) v1 = cnt;
            else if (j == 2) v2 = cnt; else v3 = cnt;
        }
    }
    int t = v0 + v1 + v2 + v3;

    int incl = t;
    #pragma unroll
    for (int s = 1; s < 32; s <<= 1) {
        int u = __shfl_up_sync(0xffffffffu, incl, s);
        if (lane >= s) incl += u;
    }
    if (lane == 31) wsum[wid] = incl;
    __syncthreads();
    if (tid == 0) {
        int run = 0;
        #pragma unroll
        for (int j = 0; j < 8; j++) { int u = wsum[j]; wsum[j] = run; run += u; }
        g_psum[b] = run;
        __threadfence();
        int ticket = atomicAdd(&g_done, 1);
        s_last = (ticket == nb - 1);
    }
    __syncthreads();

    if (s_last) {
        if (tid < 32) {
            int carry = 0;
            #pragma unroll
            for (int bb = 0; bb < SCAN_NB; bb += 32) {
                int i = bb + tid;
                int v = (i < SCAN_NB) ? ((volatile int*)g_psum)[i] : 0;
                int inc2 = v;
                #pragma unroll
                for (int st = 1; st < 32; st <<= 1) {
                    int u = __shfl_up_sync(0xffffffffu, inc2, st);
                    if (tid >= st) inc2 += u;
                }
                if (i < SCAN_NB) g_poff[i] = carry + inc2 - v;
                carry += __shfl_sync(0xffffffffu, inc2, 31);
            }
        }
        __syncthreads();
        if (tid == 0) { __threadfence(); g_flag = 1; }
    }
    if (tid == 0) { while (g_flag == 0) { } }   // 98 blocks <= 148 SMs: safe spin
    __syncthreads();

    int excl = g_poff[b] + wsum[wid] + incl - t;
    if (base + 0 < n) { g_offs[base + 0] = excl; g_cursor[base + 0] = excl; } excl += v0;
    if (base + 1 < n) { g_offs[base + 1] = excl; g_cursor[base + 1] = excl; } excl += v1;
    if (base + 2 < n) { g_offs[base + 2] = excl; g_cursor[base + 2] = excl; } excl += v2;
    if (base + 3 < n) { g_offs[base + 3] = excl; g_cursor[base + 3] = excl; }
}

// ---------------- gemm core: rows [r0,r0+4) -> fp16 h' = dinv*(x@W) ----------------
__device__ __forceinline__ void gemm_rows(const float4* __restrict__ X4,
                                          const float* __restrict__ W,
                                          ulonglong2* Ws, uint2* H2,
                                          int r0, int n, int lane) {
    unsigned long long a01[4], a23[4];
    #pragma unroll
    for (int ri = 0; ri < 4; ri++) { a01[ri] = 0ull; a23[ri] = 0ull; }

    #pragma unroll
    for (int half = 0; half < 2; half++) {
        const ulonglong2* Wh = (const ulonglong2*)(W + (size_t)half * 64 * DIM);
        for (int idx = threadIdx.x; idx < 64 * DIM4; idx += 256)
            Ws[idx] = Wh[idx];
        __syncthreads();

        if (r0 < n) {
            #pragma unroll 4
            for (int kk = 0; kk < 16; kk++) {
                ulonglong2 w0 = Ws[(4 * kk + 0) * DIM4 + lane];
                ulonglong2 w1 = Ws[(4 * kk + 1) * DIM4 + lane];
                ulonglong2 w2 = Ws[(4 * kk + 2) * DIM4 + lane];
                ulonglong2 w3 = Ws[(4 * kk + 3) * DIM4 + lane];
                #pragma unroll
                for (int ri = 0; ri < 4; ri++) {
                    int r = r0 + ri;
                    if (r < n) {
                        float4 xv = X4[(size_t)r * DIM4 + half * 16 + kk];
                        unsigned long long x0 = dup2(xv.x), x1 = dup2(xv.y);
                        unsigned long long x2 = dup2(xv.z), x3 = dup2(xv.w);
                        a01[ri] = fma2(x0, w0.x, a01[ri]); a23[ri] = fma2(x0, w0.y, a23[ri]);
                        a01[ri] = fma2(x1, w1.x, a01[ri]); a23[ri] = fma2(x1, w1.y, a23[ri]);
                        a01[ri] = fma2(x2, w2.x, a01[ri]); a23[ri] = fma2(x2, w2.y, a23[ri]);
                        a01[ri] = fma2(x3, w3.x, a01[ri]); a23[ri] = fma2(x3, w3.y, a23[ri]);
                    }
                }
            }
        }
        __syncthreads();
    }

    #pragma unroll
    for (int ri = 0; ri < 4; ri++) {
        int r = r0 + ri;
        if (r < n) {
            float dr = g_dinv[r];
            float2 c01 = unpack2(a01[ri]);
            float2 c23 = unpack2(a23[ri]);
            __half2 p0 = __floats2half2_rn(dr * c01.x, dr * c01.y);
            __half2 p1 = __floats2half2_rn(dr * c23.x, dr * c23.y);
            uint2 o; o.x = *(unsigned*)&p0; o.y = *(unsigned*)&p1;
            H2[(size_t)r * 32 + lane] = o;
        }
    }
}

// ================ fused: 1:4 interleave of gemm1 blocks and scatter blocks ================
// Both depend only on scan_all; gemm is FMA-issue-bound, scatter is L2/atomic-bound.
__global__ __launch_bounds__(256) void fused_sg_kernel(
        const float* __restrict__ x, const float* __restrict__ W1,
        const void* __restrict__ ei, const float* __restrict__ ew,
        int E, int n, int nbg) {
    __shared__ ulonglong2 Ws[64 * DIM4];  // 32KB (gemm path only)

    int b = blockIdx.x;
    int g = b / 5;
    bool isG = (b % 5 == 0) && (g < nbg);

    if (!isG) {
        // ---- scatter block ----
        int h = b - (b + 4) / 5;              // index among non-gemm blocks
        if (b % 5 == 0) h = b - g;            // overflow gemm slots (safety)
        int i = h * 256 + threadIdx.x;
        if (i < E) {
            int r = read_row(ei, E, i);
            int c = read_col(ei, E, i);
            if ((unsigned)r < (unsigned)n && (unsigned)c < (unsigned)n) {
                int pos = atomicAdd(&g_cursor[c], 1);
                if ((unsigned)pos < (unsigned)E)
                    g_edge[pos] = make_int2(r, __float_as_int(ew[i]));
            }
        }
        return;
    }

    // ---- gemm1 block: rows [g*32, g*32+32) ----
    int lane = threadIdx.x & 31, wid = threadIdx.x >> 5;
    gemm_rows((const float4*)x, W1, Ws, (uint2*)g_h16, g * 32 + wid * 4, n, lane);
}

__global__ __launch_bounds__(256) void gemm2_kernel(const float* __restrict__ W2, int n) {
    __shared__ ulonglong2 Ws[64 * DIM4];
    int lane = threadIdx.x & 31, wid = threadIdx.x >> 5;
    gemm_rows((const float4*)g_x2, W2, Ws, (uint2*)g_h16, blockIdx.x * 32 + wid * 4, n, lane);
}

// ---------------- pull aggregation: one warp per node, 2 edges/iter, unroll 4 ----------------
// out[i] = dinv[i] * ( sum_e ew_e * h'[src_e] + h'[i] ) + b ; optional relu
__global__ __launch_bounds__(256) void agg_kernel(const float* __restrict__ bias,
                                                  float* __restrict__ out_ext,
                                                  int n, int do_relu, int dst_is_x2) {
    int gw = (blockIdx.x * blockDim.x + threadIdx.x) >> 5;
    int lane = threadIdx.x & 31;
    if (gw >= n) return;
    int i = gw;
    int half = lane >> 4;    // which of 2 concurrent edges
    int li = lane & 15;      // 16B chunk within the 256B fp16 row

    int off = g_offs[i];
    int end = off + g_hist[i];

    float acc[8];
    #pragma unroll
    for (int j = 0; j < 8; j++) acc[j] = 0.0f;

    #pragma unroll 4
    for (int e0 = off; e0 < end; e0 += 2) {
        int e = e0 + half;
        if (e < end) {
            int2 ed = g_edge[e];
            float c = __int_as_float(ed.y);
            uint4 v = g_h16[(size_t)ed.x * 16 + li];
            __half2* hp = (__half2*)&v;
            float2 f0 = __half22float2(hp[0]);
            float2 f1 = __half22float2(hp[1]);
            float2 f2 = __half22float2(hp[2]);
            float2 f3 = __half22float2(hp[3]);
            acc[0] += c * f0.x; acc[1] += c * f0.y;
            acc[2] += c * f1.x; acc[3] += c * f1.y;
            acc[4] += c * f2.x; acc[5] += c * f2.y;
            acc[6] += c * f3.x; acc[7] += c * f3.y;
        }
    }
    #pragma unroll
    for (int j = 0; j < 8; j++)
        acc[j] += __shfl_xor_sync(0xffffffffu, acc[j], 16);

    float di = g_dinv[i];
    uint4 sv = g_h16[(size_t)i * 16 + li];
    __half2* sh = (__half2*)&sv;
    float2 s0 = __half22float2(sh[2 * half + 0]);
    float2 s1 = __half22float2(sh[2 * half + 1]);
    float4 b4 = ((const float4*)bias)[li * 2 + half];

    float4 r;
    r.x = di * (acc[4 * half + 0] + s0.x) + b4.x;
    r.y = di * (acc[4 * half + 1] + s0.y) + b4.y;
    r.z = di * (acc[4 * half + 2] + s1.x) + b4.z;
    r.w = di * (acc[4 * half + 3] + s1.y) + b4.w;
    if (do_relu) {
        r.x = fmaxf(r.x, 0.f); r.y = fmaxf(r.y, 0.f);
        r.z = fmaxf(r.z, 0.f); r.w = fmaxf(r.w, 0.f);
    }
    float4* dst = dst_is_x2 ? (float4*)g_x2 : (float4*)out_ext;
    dst[(size_t)i * 32 + li * 2 + half] = r;
}

// ---------------- launch (kernel launches ONLY — graph-capturable) ----------------
extern "C" void kernel_launch(void* const* d_in, const int* in_sizes, int n_in,
                              void* d_out, int out_size) {
    const float* x  = (const float*)d_in[0];
    const void*  ei = d_in[1];                 // [2, E], int32 OR int64
    const float* ew = (const float*)d_in[2];
    const float* W1 = (const float*)d_in[3];
    const float* b1 = (const float*)d_in[4];
    const float* W2 = (const float*)d_in[5];
    const float* b2 = (const float*)d_in[6];
    float* out = (float*)d_out;

    int n = in_sizes[0] / DIM;   // 100000
    int E = in_sizes[2];         // 3200000

    int nb_n    = (n + 255) / 256;
    int nb_e512 = (E + 511) / 512;
    int nb_e256 = (E + 255) / 256;   // 12500
    int nb_wn   = (n * 32 + 255) / 256;  // one warp per node
    int nb_g    = (n + 31) / 32;     // 3125  (nb_e256 == 4*nb_g)
    int nb_s    = (n + 1023) / 1024; // 98

    // preprocessing: CSR-ize edges by destination
    init_kernel<<<nb_n, 256>>>((const int*)ei, n);
    deg_hist_kernel<<<nb_e512, 512>>>(ei, ew, E, n);
    scan_all<<<nb_s, 256>>>(n, nb_s);

    // scatter ∥ gemm1 (both depend only on scan_all; disjoint pipes)
    fused_sg_kernel<<<nb_g + nb_e256, 256>>>(x, W1, ei, ew, E, n, nb_g);

    // layer 1 aggregation, layer 2 gemm + aggregation
    agg_kernel<<<nb_wn, 256>>>(b1, out, n, /*relu=*/1, /*dst_is_x2=*/1);
    gemm2_kernel<<<nb_g, 256>>>(W2, n);
    agg_kernel<<<nb_wn, 256>>>(b2, out, n, /*relu=*/0, /*dst_is_x2=*/0);
}

// round 12
// speedup vs baseline: 1.6150x; 1.5163x over previous
#include <cuda_runtime.h>
#include <cuda_fp16.h>
#include <cuda_bf16.h>
#include <stdint.h>

#define N_NODES 100000
#define N_EDGES 3200000
#define DIM 128
#define DIM4 32
#define SCAN_NB 98   // ceil(100000/1024)

// ---------------- scratch (device globals) ----------------
__device__ int                g_is64;
__device__ int                g_done;
__device__ volatile int       g_flag;
__device__ unsigned long long g_dh[N_NODES];   // [40,64) = count, [0,40) = deg 2^-24 fixed pt
__device__ float              g_dinv[N_NODES];
__device__ int                g_hist[N_NODES];
__device__ int                g_offs[N_NODES];
__device__ int                g_cursor[N_NODES];
__device__ int2               g_edge[N_EDGES];  // (src row, ew bits)
__device__ int                g_psum[128];
__device__ int                g_poff[128];
__device__ uint4              g_h16[(size_t)N_NODES * 16];  // fp16 h' = dinv*h, 128 halfs/row
__device__ float              g_x2[(size_t)N_NODES * DIM];  // layer-1 output (fp32)
__device__ __half             g_w16a[16384];   // W1^T [n][k] fp16, 16B-chunk XOR swizzled (32KB)
__device__ __half             g_w16b[16384];   // W2^T likewise

// ---------------- edge index readers (dtype-agnostic) ----------------
__device__ __forceinline__ int read_row(const void* ei, int E, int i) {
    if (g_is64) return (int)((const long long*)ei)[i];
    return ((const int*)ei)[i];
}
__device__ __forceinline__ int read_col(const void* ei, int E, int i) {
    if (g_is64) return (int)((const long long*)ei)[(size_t)E + i];
    return ((const int*)ei)[(size_t)E + i];
}

__device__ __forceinline__ uint32_t smem_u32(const void* p) {
    uint32_t a;
    asm("{ .reg .u64 t; cvta.to.shared.u64 t, %1; cvt.u32.u64 %0, t; }" : "=r"(a) : "l"(p));
    return a;
}

// ---------------- init: dh = self-loop; flags; dtype detect ----------------
__global__ void init_kernel(const int* ei_words, int n) {
    int i = blockIdx.x * blockDim.x + threadIdx.x;
    if (i < n) g_dh[i] = (1ULL << 24);
    if (i == 0) {
        g_done = 0;
        g_flag = 0;
        int is64 = 1;
        #pragma unroll 1
        for (int k = 0; k < 64; k++)
            if (ei_words[2 * k + 1] != 0) { is64 = 0; break; }
        g_is64 = is64;
    }
}

// ---------------- W prep: W^T [n][k] fp16, 16B chunks XOR-swizzled by (n&7) ----------------
__global__ void wprep_kernel(const float* __restrict__ W1, const float* __restrict__ W2) {
    int idx = blockIdx.x * blockDim.x + threadIdx.x;   // 32768
    int m = idx >> 14;
    int e = idx & 16383;
    int k = e >> 7, nn = e & 127;                       // read W[k][n], n fastest: coalesced
    float v = m ? W2[e] : W1[e];
    int chunk = (k >> 3) ^ (nn & 7);
    int off = nn * 128 + chunk * 8 + (k & 7);           // in fp16 elements
    (m ? g_w16b : g_w16a)[off] = __float2half_rn(v);
}

// ---------------- deg+hist: ONE u64 reduction per edge ----------------
__global__ void deg_hist_kernel(const void* __restrict__ ei,
                                const float* __restrict__ ew, int E, int n) {
    int i = blockIdx.x * blockDim.x + threadIdx.x;
    if (i < E) {
        int c = read_col(ei, E, i);
        if ((unsigned)c >= (unsigned)n) return;
        unsigned long long fx = (unsigned long long)__float2uint_rn(ew[i] * 16777216.0f);
        atomicAdd(&g_dh[c], (1ULL << 40) | fx);   // no return use -> REDG
    }
}

// ================ scan_all: hist/dinv/offs in ONE kernel (co-resident grid) ================
__global__ __launch_bounds__(256) void scan_all(int n, int nb) {
    __shared__ int wsum[8];
    __shared__ int s_last;
    int b = blockIdx.x, tid = threadIdx.x, lane = tid & 31, wid = tid >> 5;
    int base = b * 1024 + tid * 4;

    int v0 = 0, v1 = 0, v2 = 0, v3 = 0;
    #pragma unroll
    for (int j = 0; j < 4; j++) {
        int i = base + j;
        if (i < n) {
            unsigned long long dh = g_dh[i];
            int cnt = (int)(dh >> 40);
            g_hist[i] = cnt;
            float d = (float)(dh & 0xFFFFFFFFFFULL) * (1.0f / 16777216.0f);
            g_dinv[i] = (d > 0.0f) ? rsqrtf(d) : 0.0f;
            if (j == 0) v0 = cnt; else if (j == 1) v1 = cnt;
            else if (j == 2) v2 = cnt; else v3 = cnt;
        }
    }
    int t = v0 + v1 + v2 + v3;

    int incl = t;
    #pragma unroll
    for (int s = 1; s < 32; s <<= 1) {
        int u = __shfl_up_sync(0xffffffffu, incl, s);
        if (lane >= s) incl += u;
    }
    if (lane == 31) wsum[wid] = incl;
    __syncthreads();
    if (tid == 0) {
        int run = 0;
        #pragma unroll
        for (int j = 0; j < 8; j++) { int u = wsum[j]; wsum[j] = run; run += u; }
        g_psum[b] = run;
        __threadfence();
        int ticket = atomicAdd(&g_done, 1);
        s_last = (ticket == nb - 1);
    }
    __syncthreads();

    if (s_last) {
        if (tid < 32) {
            int carry = 0;
            #pragma unroll
            for (int bb = 0; bb < SCAN_NB; bb += 32) {
                int i = bb + tid;
                int v = (i < SCAN_NB) ? ((volatile int*)g_psum)[i] : 0;
                int inc2 = v;
                #pragma unroll
                for (int st = 1; st < 32; st <<= 1) {
                    int u = __shfl_up_sync(0xffffffffu, inc2, st);
                    if (tid >= st) inc2 += u;
                }
                if (i < SCAN_NB) g_poff[i] = carry + inc2 - v;
                carry += __shfl_sync(0xffffffffu, inc2, 31);
            }
        }
        __syncthreads();
        if (tid == 0) { __threadfence(); g_flag = 1; }
    }
    if (tid == 0) { while (g_flag == 0) { } }   // 98 blocks <= 148 SMs: safe spin
    __syncthreads();

    int excl = g_poff[b] + wsum[wid] + incl - t;
    if (base + 0 < n) { g_offs[base + 0] = excl; g_cursor[base + 0] = excl; } excl += v0;
    if (base + 1 < n) { g_offs[base + 1] = excl; g_cursor[base + 1] = excl; } excl += v1;
    if (base + 2 < n) { g_offs[base + 2] = excl; g_cursor[base + 2] = excl; } excl += v2;
    if (base + 3 < n) { g_offs[base + 3] = excl; g_cursor[base + 3] = excl; }
}

// ---------------- scatter: (row, ew) ----------------
__global__ void scatter_kernel(const void* __restrict__ ei,
                               const float* __restrict__ ew, int E, int n) {
    int i = blockIdx.x * blockDim.x + threadIdx.x;
    if (i < E) {
        int r = read_row(ei, E, i);
        int c = read_col(ei, E, i);
        if ((unsigned)r >= (unsigned)n || (unsigned)c >= (unsigned)n) return;
        int pos = atomicAdd(&g_cursor[c], 1);
        if ((unsigned)pos < (unsigned)E)
            g_edge[pos] = make_int2(r, __float_as_int(ew[i]));
    }
}

// ================ tensor-core GEMM: g_h16 = fp16(dinv * (src @ W)) ================
// block = 256 thr (8 warps x 16 rows = 128-row tile); B = W^T[n][k] fp16 in smem (swizzled)
__global__ __launch_bounds__(256) void gemm_mma_kernel(const float* __restrict__ x_ext,
                                                       int layer2, int n) {
    __shared__ __align__(16) __half sB[16384];   // 32KB

    const float* X = layer2 ? (const float*)g_x2 : x_ext;
    const __half* Wimg = layer2 ? g_w16b : g_w16a;

    int tid = threadIdx.x;
    int w = tid >> 5, lane = tid & 31;
    int g = lane >> 2, tg = lane & 3;

    // stage B image (raw copy preserves swizzle)
    {
        const uint4* src = (const uint4*)Wimg;
        uint4* dst = (uint4*)sB;
        #pragma unroll
        for (int j = 0; j < 8; j++) dst[tid + j * 256] = src[tid + j * 256];
    }
    __syncthreads();
    uint32_t sB_u = smem_u32(sB);

    int r0g = blockIdx.x * 128 + w * 16 + g;   // rows for d0/d1
    int r1g = r0g + 8;                          // rows for d2/d3
    bool v0 = r0g < n, v1 = r1g < n;
    const float* x0 = X + (size_t)(v0 ? r0g : 0) * DIM;
    const float* x1 = X + (size_t)(v1 ? r1g : 0) * DIM;

    float d[16][4];
    #pragma unroll
    for (int t = 0; t < 16; t++)
        #pragma unroll
        for (int q = 0; q < 4; q++) d[t][q] = 0.0f;

    // ldmatrix lane addressing (constant across k-steps except chunk)
    int half4 = lane >> 3;           // 0..3 : which 8x8 tile
    int nrow_lo = (half4 >> 1) * 8 + (lane & 7);   // row within 16-row n-group
    int cpar = half4 & 1;            // chunk parity (k-low/k-high 8)

    #pragma unroll
    for (int s = 0; s < 8; s++) {
        // A fragment from global fp32 -> fp16x2
        int k0 = s * 16 + tg * 2;
        float2 p00 = v0 ? *(const float2*)(x0 + k0)     : make_float2(0.f, 0.f);
        float2 p01 = v0 ? *(const float2*)(x0 + k0 + 8) : make_float2(0.f, 0.f);
        float2 p10 = v1 ? *(const float2*)(x1 + k0)     : make_float2(0.f, 0.f);
        float2 p11 = v1 ? *(const float2*)(x1 + k0 + 8) : make_float2(0.f, 0.f);
        __half2 ah0 = __floats2half2_rn(p00.x, p00.y);
        __half2 ah1 = __floats2half2_rn(p10.x, p10.y);
        __half2 ah2 = __floats2half2_rn(p01.x, p01.y);
        __half2 ah3 = __floats2half2_rn(p11.x, p11.y);
        uint32_t a0 = *(uint32_t*)&ah0, a1 = *(uint32_t*)&ah1;
        uint32_t a2 = *(uint32_t*)&ah2, a3 = *(uint32_t*)&ah3;

        int chunk = 2 * s + cpar;
        #pragma unroll
        for (int t = 0; t < 16; t += 2) {
            int nrow = t * 8 + nrow_lo;
            uint32_t addr = sB_u + (uint32_t)nrow * 256
                          + (uint32_t)((chunk ^ (nrow & 7)) << 4);
            uint32_t b0, b1, b2, b3;
            asm volatile("ldmatrix.sync.aligned.m8n8.x4.shared.b16 {%0,%1,%2,%3}, [%4];"
                         : "=r"(b0), "=r"(b1), "=r"(b2), "=r"(b3) : "r"(addr));
            asm volatile("mma.sync.aligned.m16n8k16.row.col.f32.f16.f16.f32 "
                         "{%0,%1,%2,%3}, {%4,%5,%6,%7}, {%8,%9}, {%0,%1,%2,%3};"
                         : "+f"(d[t][0]), "+f"(d[t][1]), "+f"(d[t][2]), "+f"(d[t][3])
                         : "r"(a0), "r"(a1), "r"(a2), "r"(a3), "r"(b0), "r"(b1));
            asm volatile("mma.sync.aligned.m16n8k16.row.col.f32.f16.f16.f32 "
                         "{%0,%1,%2,%3}, {%4,%5,%6,%7}, {%8,%9}, {%0,%1,%2,%3};"
                         : "+f"(d[t+1][0]), "+f"(d[t+1][1]), "+f"(d[t+1][2]), "+f"(d[t+1][3])
                         : "r"(a0), "r"(a1), "r"(a2), "r"(a3), "r"(b2), "r"(b3));
        }
    }

    // epilogue: scale by dinv, pack fp16, store
    float di0 = v0 ? g_dinv[r0g] : 0.0f;
    float di1 = v1 ? g_dinv[r1g] : 0.0f;
    unsigned* H0 = (unsigned*)g_h16 + (size_t)(v0 ? r0g : 0) * 64;
    unsigned* H1 = (unsigned*)g_h16 + (size_t)(v1 ? r1g : 0) * 64;
    #pragma unroll
    for (int t = 0; t < 16; t++) {
        int cw = t * 4 + tg;   // u32 index within row (col pair 2tg+8t)
        if (v0) {
            __half2 o = __floats2half2_rn(di0 * d[t][0], di0 * d[t][1]);
            H0[cw] = *(unsigned*)&o;
        }
        if (v1) {
            __half2 o = __floats2half2_rn(di1 * d[t][2], di1 * d[t][3]);
            H1[cw] = *(unsigned*)&o;
        }
    }
}

// ---------------- pull aggregation: one warp per node, 2 edges/iter, unroll 4 ----------------
// out[i] = dinv[i] * ( sum_e ew_e * h'[src_e] + h'[i] ) + b ; optional relu
__global__ __launch_bounds__(256) void agg_kernel(const float* __restrict__ bias,
                                                  float* __restrict__ out_ext,
                                                  int n, int do_relu, int dst_is_x2) {
    int gw = (blockIdx.x * blockDim.x + threadIdx.x) >> 5;
    int lane = threadIdx.x & 31;
    if (gw >= n) return;
    int i = gw;
    int half = lane >> 4;
    int li = lane & 15;

    int off = g_offs[i];
    int end = off + g_hist[i];

    float acc[8];
    #pragma unroll
    for (int j = 0; j < 8; j++) acc[j] = 0.0f;

    #pragma unroll 4
    for (int e0 = off; e0 < end; e0 += 2) {
        int e = e0 + half;
        if (e < end) {
            int2 ed = g_edge[e];
            float c = __int_as_float(ed.y);
            uint4 v = g_h16[(size_t)ed.x * 16 + li];
            __half2* hp = (__half2*)&v;
            float2 f0 = __half22float2(hp[0]);
            float2 f1 = __half22float2(hp[1]);
            float2 f2 = __half22float2(hp[2]);
            float2 f3 = __half22float2(hp[3]);
            acc[0] += c * f0.x; acc[1] += c * f0.y;
            acc[2] += c * f1.x; acc[3] += c * f1.y;
            acc[4] += c * f2.x; acc[5] += c * f2.y;
            acc[6] += c * f3.x; acc[7] += c * f3.y;
        }
    }
    #pragma unroll
    for (int j = 0; j < 8; j++)
        acc[j] += __shfl_xor_sync(0xffffffffu, acc[j], 16);

    float di = g_dinv[i];
    uint4 sv = g_h16[(size_t)i * 16 + li];
    __half2* sh = (__half2*)&sv;
    float2 s0 = __half22float2(sh[2 * half + 0]);
    float2 s1 = __half22float2(sh[2 * half + 1]);
    float4 b4 = ((const float4*)bias)[li * 2 + half];

    float4 r;
    r.x = di * (acc[4 * half + 0] + s0.x) + b4.x;
    r.y = di * (acc[4 * half + 1] + s0.y) + b4.y;
    r.z = di * (acc[4 * half + 2] + s1.x) + b4.z;
    r.w = di * (acc[4 * half + 3] + s1.y) + b4.w;
    if (do_relu) {
        r.x = fmaxf(r.x, 0.f); r.y = fmaxf(r.y, 0.f);
        r.z = fmaxf(r.z, 0.f); r.w = fmaxf(r.w, 0.f);
    }
    float4* dst = dst_is_x2 ? (float4*)g_x2 : (float4*)out_ext;
    dst[(size_t)i * 32 + li * 2 + half] = r;
}

// ---------------- launch (kernel launches ONLY — graph-capturable) ----------------
extern "C" void kernel_launch(void* const* d_in, const int* in_sizes, int n_in,
                              void* d_out, int out_size) {
    const float* x  = (const float*)d_in[0];
    const void*  ei = d_in[1];                 // [2, E], int32 OR int64
    const float* ew = (const float*)d_in[2];
    const float* W1 = (const float*)d_in[3];
    const float* b1 = (const float*)d_in[4];
    const float* W2 = (const float*)d_in[5];
    const float* b2 = (const float*)d_in[6];
    float* out = (float*)d_out;

    int n = in_sizes[0] / DIM;   // 100000
    int E = in_sizes[2];         // 3200000

    int nb_n  = (n + 255) / 256;
    int nb_e  = (E + 511) / 512;
    int nb_wn = (n * 32 + 255) / 256;  // one warp per node
    int nb_t  = (n + 127) / 128;       // 782 gemm tiles
    int nb_s  = (n + 1023) / 1024;     // 98

    // preprocessing: CSR-ize edges by destination; W fp16 images
    init_kernel<<<nb_n, 256>>>((const int*)ei, n);
    wprep_kernel<<<128, 256>>>(W1, W2);
    deg_hist_kernel<<<nb_e, 512>>>(ei, ew, E, n);
    scan_all<<<nb_s, 256>>>(n, nb_s);
    scatter_kernel<<<nb_e, 512>>>(ei, ew, E, n);

    // layer 1: g_h16 = fp16(dinv * (x @ W1)) ; g_x2 = agg + b1, relu
    gemm_mma_kernel<<<nb_t, 256>>>(x, /*layer2=*/0, n);
    agg_kernel<<<nb_wn, 256>>>(b1, out, n, /*relu=*/1, /*dst_is_x2=*/1);

    // layer 2: g_h16 = fp16(dinv * (g_x2 @ W2)) ; out = agg + b2
    gemm_mma_kernel<<<nb_t, 256>>>(x, /*layer2=*/1, n);
    agg_kernel<<<nb_wn, 256>>>(b2, out, n, /*relu=*/0, /*dst_is_x2=*/0);
}